// round 5
// baseline (speedup 1.0000x reference)
#include <cuda_runtime.h>
#include <math.h>

#define B_ 4
#define T_ 8
#define C_ 128
#define HW_ 9216          // 96*96
#define NBT 32            // B*T
#define NCHUNK 72
#define CHUNK 16384
#define TILEP 32
#define NTILE 288         // HW_/TILEP

typedef unsigned long long ull;

__device__ __forceinline__ ull pack2(float a, float b) {
    ull r; asm("mov.b64 %0,{%1,%2};" : "=l"(r) : "f"(a), "f"(b)); return r;
}
__device__ __forceinline__ void unpack2(ull v, float& a, float& b) {
    asm("mov.b64 {%0,%1},%2;" : "=f"(a), "=f"(b) : "l"(v));
}
__device__ __forceinline__ ull fma2(ull a, ull b, ull c) {
    ull d; asm("fma.rn.f32x2 %0,%1,%2,%3;" : "=l"(d) : "l"(a), "l"(b), "l"(c)); return d;
}
__device__ __forceinline__ ull mul2(ull a, ull b) {
    ull d; asm("mul.rn.f32x2 %0,%1,%2;" : "=l"(d) : "l"(a), "l"(b)); return d;
}

// deterministic scratch
__device__ float g_psum[NBT * NCHUNK];
__device__ float g_psq [NBT * NCHUNK];
__device__ float g_A[NBT * C_];
__device__ float g_Bc[NBT * C_];
// duplicated-pair weights: [0]=Wq, [1]=WkT*scale, [2]=Wv, [3]=proj ; each [row][k] = (w,w)
__device__ ull g_Wdup[4 * C_ * C_];

// ---------------- Kernel 1: partial sums per (b,t) chunk ----------------
__global__ __launch_bounds__(256) void reduce_kernel(const float* __restrict__ x,
                                                     const float* __restrict__ pos) {
    int bt    = blockIdx.x / NCHUNK;
    int chunk = blockIdx.x % NCHUNK;
    int t     = bt & (T_ - 1);
    const float4* x4 = (const float4*)(x + (size_t)bt * C_ * HW_);
    int base4 = chunk * (CHUNK / 4);
    float s = 0.f, sq = 0.f;
#pragma unroll
    for (int i = 0; i < 16; i++) {
        int e4 = base4 + i * 256 + threadIdx.x;
        int c  = e4 / 2304;
        float pv = pos[t * C_ + c];
        float4 v = x4[e4];
        float a0 = v.x + pv, a1 = v.y + pv, a2 = v.z + pv, a3 = v.w + pv;
        s  += (a0 + a1) + (a2 + a3);
        sq += (a0 * a0 + a1 * a1) + (a2 * a2 + a3 * a3);
    }
    __shared__ float ss[8], ssq[8];
#pragma unroll
    for (int o = 16; o; o >>= 1) {
        s  += __shfl_down_sync(0xFFFFFFFFu, s, o);
        sq += __shfl_down_sync(0xFFFFFFFFu, sq, o);
    }
    int w = threadIdx.x >> 5;
    if ((threadIdx.x & 31) == 0) { ss[w] = s; ssq[w] = sq; }
    __syncthreads();
    if (threadIdx.x == 0) {
        float S = 0.f, SQ = 0.f;
#pragma unroll
        for (int i = 0; i < 8; i++) { S += ss[i]; SQ += ssq[i]; }
        g_psum[bt * NCHUNK + chunk] = S;
        g_psq [bt * NCHUNK + chunk] = SQ;
    }
}

// ---------------- Kernel 2: finalize mean/rstd -> affine A,B ----------------
__global__ __launch_bounds__(256) void finalize_kernel(const float* __restrict__ pos,
                                                       const float* __restrict__ nw,
                                                       const float* __restrict__ nb) {
    __shared__ float sm[NBT], sr[NBT];
    int tid = threadIdx.x;
    if (tid < NBT) {
        float S = 0.f, SQ = 0.f;
        for (int i = 0; i < NCHUNK; i++) { S += g_psum[tid * NCHUNK + i]; SQ += g_psq[tid * NCHUNK + i]; }
        const float invN = 1.0f / (float)(C_ * HW_);
        float mean = S * invN;
        float var  = SQ * invN - mean * mean;
        sm[tid] = mean;
        sr[tid] = rsqrtf(var + 1e-5f);
    }
    __syncthreads();
    for (int idx = tid; idx < NBT * C_; idx += 256) {
        int bt = idx >> 7, c = idx & 127, t = bt & (T_ - 1);
        float a = sr[bt] * nw[c];
        g_A[idx]  = a;
        g_Bc[idx] = (pos[t * C_ + c] - sm[bt]) * a + nb[c];
    }
}

// ---------------- Kernel 2b: pack weights as duplicated pairs ----------------
__global__ __launch_bounds__(256) void pack_kernel(const float* __restrict__ qkv_w,
                                                   const float* __restrict__ proj_w) {
    int i   = blockIdx.x * 256 + threadIdx.x;   // 0..65535
    int m   = i >> 14;
    int idx = i & 16383;
    int r   = idx >> 7, c = idx & 127;
    float w;
    if (m == 0)      w = qkv_w[r * 128 + c];                                    // Wq
    else if (m == 1) w = qkv_w[(128 + c) * 128 + r] * 0.17677669529663687f;      // WkT[c-row=r][hd=c], scaled
    else if (m == 2) w = qkv_w[(256 + r) * 128 + c];                             // Wv
    else             w = proj_w[r * 128 + c];                                    // proj
    g_Wdup[i] = pack2(w, w);
}

// ---------------- Kernel 3: fused main ----------------
// smem float offsets
#define SM_XN   0                     // 128*32 = 4096 (t=7 tile only)
#define SM_BIG  4096                  // 4*128*32 = 16384 (U, then XBAR)
#define SM_Q    20480                 // 128*32 = 4096 (Q, then Out)
#define SM_P    24576                 // 1024 (logit partials)
#define SM_AB   25600                 // 2048 (A then B, [t*128+c])
#define SMEM_FLOATS 27648
#define SMEM_BYTES (SMEM_FLOATS * 4)  // 110592

// 4-output-row x 32-pixel packed GEMM core with pre-duplicated weights
__device__ __forceinline__ void gemm_core(const ull* __restrict__ wrow,
                                          const float* __restrict__ xsrc,
                                          int pg, int kdim, ull acc[4][2]) {
#pragma unroll
    for (int i = 0; i < 4; i++) { acc[i][0] = 0ull; acc[i][1] = 0ull; }
#pragma unroll 8
    for (int k = 0; k < kdim; k += 4) {
        ull xv[4][2];
#pragma unroll
        for (int kk = 0; kk < 4; kk++) {
            ulonglong2 v = *(const ulonglong2*)(xsrc + (k + kk) * 32 + pg * 4);
            xv[kk][0] = v.x; xv[kk][1] = v.y;
        }
#pragma unroll
        for (int i = 0; i < 4; i++) {
            ulonglong2 wa = *(const ulonglong2*)(wrow + i * C_ + k);
            ulonglong2 wb = *(const ulonglong2*)(wrow + i * C_ + k + 2);
            acc[i][0] = fma2(wa.x, xv[0][0], acc[i][0]); acc[i][1] = fma2(wa.x, xv[0][1], acc[i][1]);
            acc[i][0] = fma2(wa.y, xv[1][0], acc[i][0]); acc[i][1] = fma2(wa.y, xv[1][1], acc[i][1]);
            acc[i][0] = fma2(wb.x, xv[2][0], acc[i][0]); acc[i][1] = fma2(wb.x, xv[2][1], acc[i][1]);
            acc[i][0] = fma2(wb.y, xv[3][0], acc[i][0]); acc[i][1] = fma2(wb.y, xv[3][1], acc[i][1]);
        }
    }
}

__global__ __launch_bounds__(256, 1) void main_kernel(const float* __restrict__ x,
                                                      float* __restrict__ out) {
    extern __shared__ float sm[];
    float* sXN  = sm + SM_XN;
    float* sBig = sm + SM_BIG;
    float* sQ   = sm + SM_Q;
    float* sP   = sm + SM_P;
    float* sAB  = sm + SM_AB;

    int b    = blockIdx.x / NTILE;
    int tile = blockIdx.x % NTILE;
    int hw0  = tile * TILEP;
    int tid  = threadIdx.x;
    int cg   = tid >> 3;   // GEMM layout: 0..31
    int pg   = tid & 7;    // GEMM layout: 0..7
    int cld  = tid >> 5;   // attention layout: warp id 0..7
    int pld  = tid & 31;   // attention layout: pixel

    // ---- stage A/B affine tables for this b ----
    for (int idx = tid; idx < 1024; idx += 256) {
        sAB[idx]        = g_A [b * T_ * C_ + idx];
        sAB[1024 + idx] = g_Bc[b * T_ * C_ + idx];
    }

    // ---- Phase A: normalized tile at t=T-1 ----
    {
        int bt = b * T_ + (T_ - 1);
        const float* xb = x + (size_t)bt * C_ * HW_;
        const float* Ab = g_A  + bt * C_;
        const float* Bb = g_Bc + bt * C_;
#pragma unroll
        for (int j = 0; j < 16; j++) {
            int c = cld + j * 8;
            sXN[c * 32 + pld] = xb[c * HW_ + hw0 + pld] * Ab[c] + Bb[c];
        }
    }
    __syncthreads();

    // prefetch t=0 raw x (overlaps Q and U GEMMs)
    float xr[16];
    {
        const float* xb = x + (size_t)(b * T_) * C_ * HW_;
#pragma unroll
        for (int j = 0; j < 16; j++) xr[j] = xb[(cld + j * 8) * HW_ + hw0 + pld];
    }

    // ---- Q GEMM -> sQ ----
    {
        ull acc[4][2];
        gemm_core(g_Wdup + (size_t)(cg * 4) * C_, sXN, pg, 128, acc);
#pragma unroll
        for (int i = 0; i < 4; i++) {
            ulonglong2 o; o.x = acc[i][0]; o.y = acc[i][1];
            *(ulonglong2*)(sQ + (cg * 4 + i) * 32 + pg * 4) = o;
        }
    }
    __syncthreads();

    // ---- U_h[c][p] = sum_d WkT[c][h*32+d]*Q[h*32+d][p] -> sBig ----
#pragma unroll
    for (int h = 0; h < 4; h++) {
        ull acc[4][2];
        gemm_core(g_Wdup + 16384 + (size_t)(cg * 4) * C_ + h * 32, sQ + h * 1024, pg, 32, acc);
#pragma unroll
        for (int i = 0; i < 4; i++) {
            ulonglong2 o; o.x = acc[i][0]; o.y = acc[i][1];
            *(ulonglong2*)(sBig + h * 4096 + (cg * 4 + i) * 32 + pg * 4) = o;
        }
    }
    __syncthreads();

    // ---- load U into registers (attention layout), packed over c-pairs (c, c+8) ----
    ull uP[4][8];
#pragma unroll
    for (int h = 0; h < 4; h++)
#pragma unroll
        for (int jj = 0; jj < 8; jj++) {
            float a0 = sBig[h * 4096 + (cld + 16 * jj    ) * 32 + pld];
            float a1 = sBig[h * 4096 + (cld + 16 * jj + 8) * 32 + pld];
            uP[h][jj] = pack2(a0, a1);
        }

    // xn for t=7 from sXN, packed same way
    ull xnP[8];
#pragma unroll
    for (int jj = 0; jj < 8; jj++) {
        float a0 = sXN[(cld + 16 * jj    ) * 32 + pld];
        float a1 = sXN[(cld + 16 * jj + 8) * 32 + pld];
        xnP[jj] = pack2(a0, a1);
    }

    // register-resident online softmax + xbar accumulation
    ull   xbarP[4][8];
#pragma unroll
    for (int h = 0; h < 4; h++)
#pragma unroll
        for (int jj = 0; jj < 8; jj++) xbarP[h][jj] = 0ull;
    float m_run[4] = {-1e30f, -1e30f, -1e30f, -1e30f};
    float s_run[4] = {0.f, 0.f, 0.f, 0.f};

    for (int it = 0; it < T_; it++) {
        int s = (it == 0) ? (T_ - 1) : (it - 1);
        if (it > 0) {
            // normalize xr -> xnP (registers only)
            const float* As = sAB + s * 128;
            const float* Bs = sAB + 1024 + s * 128;
#pragma unroll
            for (int jj = 0; jj < 8; jj++) {
                int c0 = cld + 16 * jj;
                float a0 = xr[2 * jj]     * As[c0]     + Bs[c0];
                float a1 = xr[2 * jj + 1] * As[c0 + 8] + Bs[c0 + 8];
                xnP[jj] = pack2(a0, a1);
            }
        }
        if (it >= 1 && it < T_ - 1) {   // prefetch raw x for t=it (used next iter)
            const float* xb = x + (size_t)(b * T_ + it) * C_ * HW_;
#pragma unroll
            for (int jj = 0; jj < 8; jj++) {
                xr[2 * jj]     = xb[(cld + 16 * jj    ) * HW_ + hw0 + pld];
                xr[2 * jj + 1] = xb[(cld + 16 * jj + 8) * HW_ + hw0 + pld];
            }
        }

        // logit partials over this thread's 16 c (pure register fma2)
        ull lg[4] = {0ull, 0ull, 0ull, 0ull};
#pragma unroll
        for (int jj = 0; jj < 8; jj++) {
            lg[0] = fma2(xnP[jj], uP[0][jj], lg[0]);
            lg[1] = fma2(xnP[jj], uP[1][jj], lg[1]);
            lg[2] = fma2(xnP[jj], uP[2][jj], lg[2]);
            lg[3] = fma2(xnP[jj], uP[3][jj], lg[3]);
        }
        float4 part;
        { float lo, hi;
          unpack2(lg[0], lo, hi); part.x = lo + hi;
          unpack2(lg[1], lo, hi); part.y = lo + hi;
          unpack2(lg[2], lo, hi); part.z = lo + hi;
          unpack2(lg[3], lo, hi); part.w = lo + hi; }
        *(float4*)(sP + (cld * 32 + pld) * 4) = part;
        __syncthreads();

        // reduce 8 partials (all threads of a pixel do it redundantly, identically)
        float L[4] = {0.f, 0.f, 0.f, 0.f};
#pragma unroll
        for (int k = 0; k < 8; k++) {
            float4 v = *(const float4*)(sP + (k * 32 + pld) * 4);
            L[0] += v.x; L[1] += v.y; L[2] += v.z; L[3] += v.w;
        }
        __syncthreads();   // sP free for next iteration

        // per-head softmax state + xbar update (registers only, fast exp)
#pragma unroll
        for (int h = 0; h < 4; h++) {
            float mn   = fmaxf(m_run[h], L[h]);
            float corr = __expf(m_run[h] - mn);
            float e    = __expf(L[h] - mn);
            s_run[h] = s_run[h] * corr + e;
            m_run[h] = mn;
            ull cP = pack2(corr, corr);
            ull eP = pack2(e, e);
#pragma unroll
            for (int jj = 0; jj < 8; jj++)
                xbarP[h][jj] = fma2(eP, xnP[jj], mul2(cP, xbarP[h][jj]));
        }
    }

    // normalize xbar and write to sBig (U no longer needed)
#pragma unroll
    for (int h = 0; h < 4; h++) {
        float inv = 1.0f / s_run[h];
        ull iP = pack2(inv, inv);
#pragma unroll
        for (int jj = 0; jj < 8; jj++) {
            float lo, hi;
            unpack2(mul2(iP, xbarP[h][jj]), lo, hi);
            sBig[h * 4096 + (cld + 16 * jj    ) * 32 + pld] = lo;
            sBig[h * 4096 + (cld + 16 * jj + 8) * 32 + pld] = hi;
        }
    }
    __syncthreads();

    // ---- Phase E: Out[hd][p] = Wv . xbar_h -> sQ ----
    {
        ull acc[4][2];
        gemm_core(g_Wdup + 2 * 16384 + (size_t)(cg * 4) * C_, sBig + (cg >> 3) * 4096, pg, 128, acc);
#pragma unroll
        for (int i = 0; i < 4; i++) {
            ulonglong2 o; o.x = acc[i][0]; o.y = acc[i][1];
            *(ulonglong2*)(sQ + (cg * 4 + i) * 32 + pg * 4) = o;
        }
    }
    __syncthreads();

    // ---- Phase F: projection -> gmem ----
    {
        ull acc[4][2];
        gemm_core(g_Wdup + 3 * 16384 + (size_t)(cg * 4) * C_, sQ, pg, 128, acc);
#pragma unroll
        for (int i = 0; i < 4; i++) {
            ulonglong2 o; o.x = acc[i][0]; o.y = acc[i][1];
            *(ulonglong2*)(out + ((size_t)b * C_ + cg * 4 + i) * HW_ + hw0 + pg * 4) = o;
        }
    }
}

extern "C" void kernel_launch(void* const* d_in, const int* in_sizes, int n_in,
                              void* d_out, int out_size) {
    const float* x    = (const float*)d_in[0];
    const float* pos  = (const float*)d_in[1];
    const float* nw   = (const float*)d_in[2];
    const float* nb   = (const float*)d_in[3];
    const float* qkvw = (const float*)d_in[4];
    const float* pw   = (const float*)d_in[5];
    float* out = (float*)d_out;

    reduce_kernel<<<NBT * NCHUNK, 256>>>(x, pos);
    finalize_kernel<<<1, 256>>>(pos, nw, nb);
    pack_kernel<<<256, 256>>>(qkvw, pw);
    cudaFuncSetAttribute(main_kernel, cudaFuncAttributeMaxDynamicSharedMemorySize, SMEM_BYTES);
    main_kernel<<<B_ * NTILE, 256, SMEM_BYTES>>>(x, out);
}